// round 15
// baseline (speedup 1.0000x reference)
#include <cuda_runtime.h>
#include <cuda_bf16.h>
#include <cstdint>
#include <cstddef>

// Problem constants: B=32, N=4096, D_U=64, D=128, H=2, DH=64
#define BATCH 32
#define SEQN 4096
#define TILES 32
#define NWORK (TILES * BATCH)

typedef unsigned long long ULL;

// ---- arch-feature gate: tcgen05 only exists on 'a'/'f' suffixed targets ----
#if defined(__CUDA_ARCH__) && (__CUDA_ARCH__ >= 1000) && \
    (defined(__CUDA_ARCH_FEAT_SM103_ALL) || defined(__CUDA_ARCH_FEAT_SM100_ALL) || \
     defined(__CUDA_ARCH_SPECIFIC__) || defined(__CUDA_ARCH_FAMILY_SPECIFIC__))
#define TC_OK 1
#else
#define TC_OK 0
#endif

// ---------------- TMEM column layout: 512 cols ----------------
#define T_A2HI 0
#define T_A2LO 64
#define T_D1   128
#define T_D2   256
#define TMEM_COLS 512

// ---------------- SMEM layout (bytes), R6-style: 1 CTA/SM ----------------
#define S_A1HI 0          /* 16 KB, dead after GEMM1 */
#define S_A1LO 16384      /* 16 KB */
#define S_B1HI 32768      /* 16 KB, dead after GEMM1 */
#define S_B1LO 49152      /* 16 KB */
#define S_Z2   0          /* fp32 z2, 128 x stride129 = 66048 B (overlays A1/B1) */
#define S_B2HI 66560      /* 32 KB, separate region -> copy overlaps GEMM1 */
#define S_B2LO 99328      /* 32 KB */
#define S_AVEC 132096     /* a_h vectors: 2 x 128 fp32 */
#define S_SS   133120     /* scores 128 x 2 fp32 */
#define S_SP   134144     /* score partials (2048 B); also bootstrap red/sq scratch */
#define S_CTRL 136192     /* tmem ptr @0, mbar @8, c[2] @16 */
#define S_B1B  136256     /* b1 128 fp32 */
#define S_B2B  136768     /* b2 128 fp32 */
#define S_TOTAL 137280

// idesc: F32 accum, BF16 a/b, N=128, M=128, cta_group::1
#define IDESC ((1u<<4)|(1u<<7)|(1u<<10)|(16u<<17)|(8u<<24))

// ---------------- global scratch (no allocations allowed) ----------------
__device__ float g_a[2 * 128];
__device__ float g_c[2];
__device__ float g_mp[NWORK * 256];
__device__ float g_Sp[NWORK * 2];
__device__ int g_ready;     // per-call bootstrap flag; reset by finish_kernel
// Swizzled SMEM byte-images of W1^T / W2^T as split bf16 (built by CTA0 in-main).
__device__ __align__(16) __nv_bfloat16 g_B1hi[128 * 64];
__device__ __align__(16) __nv_bfloat16 g_B1lo[128 * 64];
__device__ __align__(16) __nv_bfloat16 g_B2hi[128 * 128];
__device__ __align__(16) __nv_bfloat16 g_B2lo[128 * 128];

// ---------------- common helpers ----------------
__device__ __forceinline__ float gelu_f(float x) {
    float x2 = x * x;
    float inner = fmaf(0.044715f * x2, x, x);
    float arg = 0.7978845608028654f * inner;
    float t;
    asm("tanh.approx.f32 %0, %1;" : "=f"(t) : "f"(arg));
    return 0.5f * x * (1.0f + t);
}
__device__ __forceinline__ uint32_t swz(uint32_t byte_off) {
    return byte_off ^ ((byte_off >> 3) & 0x70);
}
__device__ __forceinline__ uint32_t pk_bf(float a, float b) {
    return (uint32_t)__bfloat16_as_ushort(__float2bfloat16_rn(a)) |
           ((uint32_t)__bfloat16_as_ushort(__float2bfloat16_rn(b)) << 16);
}

#if TC_OK
// ---------------- tcgen05 PTX helpers (only compiled on 'a'/'f' targets) ----
__device__ __forceinline__ uint32_t elect_one_pred() {
    uint32_t pred;
    asm volatile(
        "{\n\t.reg .pred p;\n\telect.sync _|p, 0xFFFFFFFF;\n\t"
        "selp.b32 %0, 1, 0, p;\n\t}" : "=r"(pred));
    return pred;
}
__device__ __forceinline__ uint32_t smem_to_u32(const void* p) {
    uint32_t a;
    asm("{ .reg .u64 t; cvta.to.shared.u64 t, %1; cvt.u32.u64 %0, t; }" : "=r"(a) : "l"(p));
    return a;
}
static constexpr uint64_t SMEM_DESC_BASE_SW128 =
    (uint64_t(2) << 61) | (uint64_t(1) << 46) | (uint64_t(64) << 32) | (uint64_t(1) << 16);
#define MAKE_SMEM_DESC(base_addr) \
    (SMEM_DESC_BASE_SW128 | ((uint64_t)((base_addr) >> 4) & 0x3FFF))

#define TCGEN05_ALLOC(smem_addr, nCols) \
    asm volatile("tcgen05.alloc.cta_group::1.sync.aligned.shared::cta.b32 [%0], %1;" \
        :: "r"((uint32_t)(smem_addr)), "r"((uint32_t)(nCols)) : "memory")
#define TCGEN05_DEALLOC(tmem_addr, nCols) \
    asm volatile("tcgen05.dealloc.cta_group::1.sync.aligned.b32 %0, %1;" \
        :: "r"(tmem_addr), "r"((uint32_t)(nCols)))
#define TCGEN05_COMMIT(mbar) \
    asm volatile("tcgen05.commit.cta_group::1.mbarrier::arrive::one.shared::cluster.b64 [%0];" \
        :: "r"((uint32_t)(mbar)) : "memory")
#define TCGEN05_WAIT_LD()  asm volatile("tcgen05.wait::ld.sync.aligned;" ::: "memory")
#define TCGEN05_WAIT_ST()  asm volatile("tcgen05.wait::st.sync.aligned;" ::: "memory")
#define TCGEN05_FENCE_BEFORE() asm volatile("tcgen05.fence::before_thread_sync;" ::: "memory")
#define TCGEN05_FENCE_AFTER()  asm volatile("tcgen05.fence::after_thread_sync;" ::: "memory")
#define MBARRIER_INIT(mbar, count) \
    asm volatile("mbarrier.init.shared.b64 [%0], %1;" \
        :: "r"((uint32_t)(mbar)), "r"((uint32_t)(count)) : "memory")
#define MBARRIER_INVAL(mbar) \
    asm volatile("mbarrier.inval.shared.b64 [%0];" :: "r"((uint32_t)(mbar)) : "memory")

#define MBARRIER_WAIT_PARITY(mbar_smem_addr, phase_parity) do { \
    uint32_t _mbar = (uint32_t)(mbar_smem_addr); \
    uint32_t _parity = (uint32_t)(phase_parity); \
    uint32_t _done; \
    asm volatile( \
        "{\n\t.reg .pred p;\n\t" \
        "mbarrier.try_wait.parity.acquire.cta.shared::cta.b64 p, [%1], %2;\n\t" \
        "selp.b32 %0, 1, 0, p;\n\t}" \
        : "=r"(_done) : "r"(_mbar), "r"(_parity) : "memory"); \
    if (!_done) { \
        asm volatile( \
            "{\n\t.reg .pred P1;\n\t" \
            "WAIT_LOOP_%=:\n\t" \
            "mbarrier.try_wait.parity.acquire.cta.shared::cta.b64 P1, [%0], %1, 0x989680;\n\t" \
            "@P1 bra.uni WAIT_DONE_%=;\n\t" \
            "bra.uni WAIT_LOOP_%=;\n\t" \
            "WAIT_DONE_%=:\n\t}" \
            :: "r"(_mbar), "r"(_parity) : "memory"); \
    } \
} while (0)

#define TCGEN05_LD_32X32B_X32(r, tmem_addr) \
    asm volatile( \
        "tcgen05.ld.sync.aligned.32x32b.x32.b32 " \
        "{%0, %1, %2, %3, %4, %5, %6, %7, " \
        " %8, %9, %10, %11, %12, %13, %14, %15, " \
        " %16, %17, %18, %19, %20, %21, %22, %23, " \
        " %24, %25, %26, %27, %28, %29, %30, %31}, [%32];" \
        : "=r"((r)[0]),  "=r"((r)[1]),  "=r"((r)[2]),  "=r"((r)[3]), \
          "=r"((r)[4]),  "=r"((r)[5]),  "=r"((r)[6]),  "=r"((r)[7]), \
          "=r"((r)[8]),  "=r"((r)[9]),  "=r"((r)[10]), "=r"((r)[11]), \
          "=r"((r)[12]), "=r"((r)[13]), "=r"((r)[14]), "=r"((r)[15]), \
          "=r"((r)[16]), "=r"((r)[17]), "=r"((r)[18]), "=r"((r)[19]), \
          "=r"((r)[20]), "=r"((r)[21]), "=r"((r)[22]), "=r"((r)[23]), \
          "=r"((r)[24]), "=r"((r)[25]), "=r"((r)[26]), "=r"((r)[27]), \
          "=r"((r)[28]), "=r"((r)[29]), "=r"((r)[30]), "=r"((r)[31]) \
        : "r"(tmem_addr))

#define TCGEN05_ST_32X32B_X16(tmem_addr, r) \
    asm volatile( \
        "tcgen05.st.sync.aligned.32x32b.x16.b32 [%0], " \
        "{%1, %2, %3, %4, %5, %6, %7, %8, " \
        " %9, %10, %11, %12, %13, %14, %15, %16};" \
        :: "r"(tmem_addr), \
           "r"((r)[0]),  "r"((r)[1]),  "r"((r)[2]),  "r"((r)[3]), \
           "r"((r)[4]),  "r"((r)[5]),  "r"((r)[6]),  "r"((r)[7]), \
           "r"((r)[8]),  "r"((r)[9]),  "r"((r)[10]), "r"((r)[11]), \
           "r"((r)[12]), "r"((r)[13]), "r"((r)[14]), "r"((r)[15]) \
        : "memory")

__device__ __forceinline__ void mma_f16_ss(uint32_t d, uint64_t ad, uint64_t bd,
                                           uint32_t idesc, uint32_t en) {
    asm volatile(
        "{\n\t.reg .pred p;\n\tsetp.ne.u32 p, %4, 0;\n\t"
        "tcgen05.mma.cta_group::1.kind::f16 [%0], %1, %2, %3, {%5, %5, %5, %5}, p;\n\t}"
        :: "r"(d), "l"(ad), "l"(bd), "r"(idesc), "r"(en), "r"(0u) : "memory");
}
__device__ __forceinline__ void mma_f16_ts(uint32_t d, uint32_t at, uint64_t bd,
                                           uint32_t idesc, uint32_t en) {
    asm volatile(
        "{\n\t.reg .pred p;\n\tsetp.ne.u32 p, %4, 0;\n\t"
        "tcgen05.mma.cta_group::1.kind::f16 [%0], [%1], %2, %3, {%5, %5, %5, %5}, p;\n\t}"
        :: "r"(d), "r"(at), "l"(bd), "r"(idesc), "r"(en), "r"(0u) : "memory");
}
#endif  // TC_OK

// ---------------- main kernel: no prep launch; CTA(0,0) bootstraps ----------------
__global__ void __launch_bounds__(256, 1)
main_kernel(const float* __restrict__ u,
            const float* __restrict__ W1, const float* __restrict__ b1,
            const float* __restrict__ W2, const float* __restrict__ b2,
            const float* __restrict__ embed,
            const float* __restrict__ Wq, const float* __restrict__ bq,
            const float* __restrict__ Wk, const float* __restrict__ bk) {
#if TC_OK
    extern __shared__ char sb[];
    const int tid = threadIdx.x;
    const int w = tid >> 5;
    const int lane = tid & 31;
    const int tile = blockIdx.x;
    const int b = blockIdx.y;
    const bool boot = (tile == 0) && (b == 0);
    uint32_t sb32 = smem_to_u32(sb);

    if (w == 0) TCGEN05_ALLOC(sb32 + S_CTRL, TMEM_COLS);
    if (tid == 0) MBARRIER_INIT(sb32 + S_CTRL + 8, 1);

    // ---- phase 0a: u tile -> split-bf16 A1 (SW128 K-major) ----
    {
        int row = tid >> 1, kh = (tid & 1) << 5;
        const float4* up = (const float4*)(u + ((size_t)b * SEQN + (size_t)tile * 128 + row) * 64 + kh);
        #pragma unroll
        for (int i = 0; i < 8; i++) {
            float4 v = up[i];
            __nv_bfloat16 h0 = __float2bfloat16_rn(v.x), h1 = __float2bfloat16_rn(v.y);
            __nv_bfloat16 h2 = __float2bfloat16_rn(v.z), h3 = __float2bfloat16_rn(v.w);
            uint32_t hiA = (uint32_t)__bfloat16_as_ushort(h0) | ((uint32_t)__bfloat16_as_ushort(h1) << 16);
            uint32_t hiB = (uint32_t)__bfloat16_as_ushort(h2) | ((uint32_t)__bfloat16_as_ushort(h3) << 16);
            uint32_t loA = pk_bf(v.x - __bfloat162float(h0), v.y - __bfloat162float(h1));
            uint32_t loB = pk_bf(v.z - __bfloat162float(h2), v.w - __bfloat162float(h3));
            uint32_t sw = swz((uint32_t)(row * 128 + (kh + 4 * i) * 2));
            *(ULL*)(sb + S_A1HI + sw) = (ULL)hiA | ((ULL)hiB << 32);
            *(ULL*)(sb + S_A1LO + sw) = (ULL)loA | ((ULL)loB << 32);
        }
    }

    if (boot) {
        // ==== bootstrap: a/c vectors + W1/W2 split-bf16 images (own smem + global) ====
        float* red = (float*)(sb + S_SP);
        float* sq  = (float*)(sb + S_SP + 1024);
        {
            int tt = tid & 127, p = tid >> 7;
            int c0 = p * 64;
            float acc = 0.f;
            #pragma unroll
            for (int c = 0; c < 64; c++)
                acc = fmaf(embed[c0 + c], Wq[(c0 + c) * 128 + tt], acc);
            red[p * 128 + tt] = acc;
        }
        __syncthreads();
        if (tid < 128) sq[tid] = bq[tid] + red[tid] + red[128 + tid];
        __syncthreads();
        {
            int tt = tid & 127, h = tid >> 7;
            float a = 0.f;
            #pragma unroll
            for (int d = 0; d < 64; d++)
                a = fmaf(Wk[tt * 128 + h * 64 + d], sq[h * 64 + d], a);
            g_a[h * 128 + tt] = a;
        }
        if (tid < 2) {
            float c0 = 0.f;
            #pragma unroll
            for (int d = 0; d < 64; d++) c0 = fmaf(bk[tid * 64 + d], sq[tid * 64 + d], c0);
            g_c[tid] = c0;
        }
        // W1 -> sB1 (K-major SW128 image)
        #pragma unroll 8
        for (int i = 0; i < 32; i++) {
            int idx = tid + 256 * i;            // k = idx>>7, n = idx&127
            int k = idx >> 7, n = idx & 127;
            float wv = W1[idx];
            __nv_bfloat16 h = __float2bfloat16_rn(wv);
            __nv_bfloat16 l = __float2bfloat16_rn(wv - __bfloat162float(h));
            uint32_t loc = swz((uint32_t)(n * 128 + k * 2));
            *(__nv_bfloat16*)(sb + S_B1HI + loc) = h;
            *(__nv_bfloat16*)(sb + S_B1LO + loc) = l;
        }
        // W2 -> sB2 (blocked SW128 atoms, atom_col = k>>6 at +16KB)
        #pragma unroll 8
        for (int i = 0; i < 64; i++) {
            int idx = tid + 256 * i;
            int k = idx >> 7, n = idx & 127;
            float wv = W2[idx];
            __nv_bfloat16 h = __float2bfloat16_rn(wv);
            __nv_bfloat16 l = __float2bfloat16_rn(wv - __bfloat162float(h));
            uint32_t byte = ((uint32_t)(k >> 6) << 14) + ((uint32_t)(n >> 3) << 10)
                          + ((uint32_t)(n & 7) << 7) + ((uint32_t)(k & 63) << 1);
            uint32_t loc = swz(byte);
            *(__nv_bfloat16*)(sb + S_B2HI + loc) = h;
            *(__nv_bfloat16*)(sb + S_B2LO + loc) = l;
        }
        __syncthreads();
        // publish images (coalesced float4 stores)
        {
            #pragma unroll
            for (int i = 0; i < 4; i++) {
                ((float4*)g_B1hi)[tid + i * 256] = ((const float4*)(sb + S_B1HI))[tid + i * 256];
                ((float4*)g_B1lo)[tid + i * 256] = ((const float4*)(sb + S_B1LO))[tid + i * 256];
            }
            #pragma unroll
            for (int i = 0; i < 8; i++) {
                ((float4*)g_B2hi)[tid + i * 256] = ((const float4*)(sb + S_B2HI))[tid + i * 256];
                ((float4*)g_B2lo)[tid + i * 256] = ((const float4*)(sb + S_B2LO))[tid + i * 256];
            }
        }
        __threadfence();
        __syncthreads();
        if (tid == 0)
            asm volatile("st.release.gpu.global.b32 [%0], %1;" :: "l"(&g_ready), "r"(1) : "memory");
    } else {
        // ==== wait for bootstrap, then copy B1 image ====
        if (tid == 0) {
            int v;
            do {
                asm volatile("ld.acquire.gpu.global.b32 %0, [%1];" : "=r"(v) : "l"(&g_ready) : "memory");
                if (!v) __nanosleep(64);
            } while (!v);
        }
        __syncthreads();
        {
            const float4* gh = (const float4*)g_B1hi;
            const float4* gl = (const float4*)g_B1lo;
            float4* sh = (float4*)(sb + S_B1HI);
            float4* sl = (float4*)(sb + S_B1LO);
            #pragma unroll
            for (int i = 0; i < 4; i++) {
                sh[tid + i * 256] = gh[tid + i * 256];
                sl[tid + i * 256] = gl[tid + i * 256];
            }
        }
    }

    ((float*)(sb + S_AVEC))[tid] = g_a[tid];
    if (tid < 128) {
        ((float*)(sb + S_B1B))[tid] = b1[tid];
        ((float*)(sb + S_B2B))[tid] = b2[tid];
    }
    if (tid < 2) ((float*)(sb + S_CTRL + 16))[tid] = g_c[tid];
    asm volatile("fence.proxy.async.shared::cta;" ::: "memory");
    __syncthreads();

    uint32_t tbase;
    asm volatile("ld.shared.b32 %0, [%1];" : "=r"(tbase) : "r"(sb32 + S_CTRL));

    // ---- GEMM1: D1 = A1 @ B1^T  (3 split terms x 4 K-chunks, SS mode) ----
    if (w == 0) {
        uint64_t aH = MAKE_SMEM_DESC(sb32 + S_A1HI), aL = MAKE_SMEM_DESC(sb32 + S_A1LO);
        uint64_t bH = MAKE_SMEM_DESC(sb32 + S_B1HI), bL = MAKE_SMEM_DESC(sb32 + S_B1LO);
        if (elect_one_pred()) {
            #pragma unroll
            for (int k = 0; k < 4; k++) mma_f16_ss(tbase + T_D1, aH + 2 * k, bH + 2 * k, IDESC, k > 0);
            #pragma unroll
            for (int k = 0; k < 4; k++) mma_f16_ss(tbase + T_D1, aH + 2 * k, bL + 2 * k, IDESC, 1);
            #pragma unroll
            for (int k = 0; k < 4; k++) mma_f16_ss(tbase + T_D1, aL + 2 * k, bH + 2 * k, IDESC, 1);
            TCGEN05_COMMIT(sb32 + S_CTRL + 8);
        }
    }
    // ---- copy B2 image while GEMM1 runs (separate smem region; boot has it) ----
    if (!boot) {
        const float4* gh = (const float4*)g_B2hi;
        const float4* gl = (const float4*)g_B2lo;
        float4* sh = (float4*)(sb + S_B2HI);
        float4* sl = (float4*)(sb + S_B2LO);
        #pragma unroll
        for (int i = 0; i < 8; i++) {
            sh[tid + i * 256] = gh[tid + i * 256];
            sl[tid + i * 256] = gl[tid + i * 256];
        }
    }
    asm volatile("fence.proxy.async.shared::cta;" ::: "memory");

    MBARRIER_WAIT_PARITY(sb32 + S_CTRL + 8, 0);
    TCGEN05_FENCE_AFTER();

    // ---- epilogue 1: z1 = gelu(D1+b1) -> split bf16 -> TMEM A2 (TS operand) ----
    const int part = w & 3;
    const int cbase = (w >> 2) * 64;
    const int r = part * 32 + lane;
    const uint32_t sttm = ((uint32_t)part) << 21;
    {
        const float* b1s = (const float*)(sb + S_B1B);
        #pragma unroll
        for (int ch = 0; ch < 2; ch++) {
            int c0 = cbase + 32 * ch;
            uint32_t d[32];
            TCGEN05_LD_32X32B_X32(d, tbase + T_D1 + c0);
            TCGEN05_WAIT_LD();
            uint32_t hi[16], lo[16];
            #pragma unroll
            for (int j = 0; j < 16; j++) {
                float z0 = gelu_f(__uint_as_float(d[2 * j]) + b1s[c0 + 2 * j]);
                float z1 = gelu_f(__uint_as_float(d[2 * j + 1]) + b1s[c0 + 2 * j + 1]);
                __nv_bfloat16 h0 = __float2bfloat16_rn(z0), h1 = __float2bfloat16_rn(z1);
                hi[j] = (uint32_t)__bfloat16_as_ushort(h0) | ((uint32_t)__bfloat16_as_ushort(h1) << 16);
                lo[j] = pk_bf(z0 - __bfloat162float(h0), z1 - __bfloat162float(h1));
            }
            TCGEN05_ST_32X32B_X16(tbase + T_A2HI + (c0 >> 1) + sttm, hi);
            TCGEN05_ST_32X32B_X16(tbase + T_A2LO + (c0 >> 1) + sttm, lo);
        }
        TCGEN05_WAIT_ST();
    }
    TCGEN05_FENCE_BEFORE();
    __syncthreads();

    // ---- GEMM2: D2 = A2 @ B2^T  (3 split terms x 8 K-chunks, TS mode) ----
    if (w == 0) {
        TCGEN05_FENCE_AFTER();
        uint64_t bH = MAKE_SMEM_DESC(sb32 + S_B2HI), bL = MAKE_SMEM_DESC(sb32 + S_B2LO);
        if (elect_one_pred()) {
            #pragma unroll
            for (int k = 0; k < 8; k++) {
                uint64_t o = (k < 4) ? (uint64_t)(2 * k) : (uint64_t)(1024 + 2 * (k - 4));
                mma_f16_ts(tbase + T_D2, tbase + T_A2HI + 8 * k, bH + o, IDESC, k > 0);
            }
            #pragma unroll
            for (int k = 0; k < 8; k++) {
                uint64_t o = (k < 4) ? (uint64_t)(2 * k) : (uint64_t)(1024 + 2 * (k - 4));
                mma_f16_ts(tbase + T_D2, tbase + T_A2HI + 8 * k, bL + o, IDESC, 1);
            }
            #pragma unroll
            for (int k = 0; k < 8; k++) {
                uint64_t o = (k < 4) ? (uint64_t)(2 * k) : (uint64_t)(1024 + 2 * (k - 4));
                mma_f16_ts(tbase + T_D2, tbase + T_A2LO + 8 * k, bH + o, IDESC, 1);
            }
            TCGEN05_COMMIT(sb32 + S_CTRL + 8);
        }
    }
    MBARRIER_WAIT_PARITY(sb32 + S_CTRL + 8, 1);
    TCGEN05_FENCE_AFTER();

    // ---- epilogue 2: z2 = gelu(D2+b2); score partials; z2 -> smem (stride 129) ----
    {
        float* z2s = (float*)(sb + S_Z2);
        const float* av = (const float*)(sb + S_AVEC);
        const float* b2s = (const float*)(sb + S_B2B);
        float sp0 = 0.f, sp1 = 0.f;
        #pragma unroll
        for (int ch = 0; ch < 2; ch++) {
            int c0 = cbase + 32 * ch;
            uint32_t d[32];
            TCGEN05_LD_32X32B_X32(d, tbase + T_D2 + c0);
            TCGEN05_WAIT_LD();
            #pragma unroll
            for (int j = 0; j < 32; j++) {
                float z = gelu_f(__uint_as_float(d[j]) + b2s[c0 + j]);
                z2s[r * 129 + c0 + j] = z;
                sp0 = fmaf(av[c0 + j], z, sp0);
                sp1 = fmaf(av[128 + c0 + j], z, sp1);
            }
        }
        float* sSp = (float*)(sb + S_SP);
        sSp[r * 4 + (w >> 2) * 2 + 0] = sp0;
        sSp[r * 4 + (w >> 2) * 2 + 1] = sp1;
    }
    __syncthreads();

    // combine score halves: s[r][h] = c_h + sp[r][0][h] + sp[r][1][h]
    {
        float* sS = (float*)(sb + S_SS);
        const float* sSp = (const float*)(sb + S_SP);
        const float* cs = (const float*)(sb + S_CTRL + 16);
        int r2 = tid >> 1, h = tid & 1;
        sS[r2 * 2 + h] = cs[h] + sSp[r2 * 4 + h] + sSp[r2 * 4 + 2 + h];
    }
    __syncthreads();

    // phase 4: m_h[col] = sum_r s[r][h] * z2[r][col]
    {
        const float* sS = (const float*)(sb + S_SS);
        const float* z2s = (const float*)(sb + S_Z2);
        int h = tid >> 7, col = tid & 127;
        float m = 0.f;
        #pragma unroll 4
        for (int rr = 0; rr < 128; rr++) m = fmaf(sS[rr * 2 + h], z2s[rr * 129 + col], m);
        g_mp[((size_t)(tile * BATCH + b)) * 256 + tid] = m;
        if (tid < 2) {
            float S = 0.f;
            #pragma unroll 4
            for (int rr = 0; rr < 128; rr++) S += sS[rr * 2 + tid];
            g_Sp[(tile * BATCH + b) * 2 + tid] = S;
        }
    }

    __syncthreads();
    if (tid == 0) MBARRIER_INVAL(sb32 + S_CTRL + 8);
    __syncthreads();
    if (w == 0) TCGEN05_DEALLOC(tbase, TMEM_COLS);

#else
    // ================= compact fallback (never runs on sm_103a) =================
    // Computes a/c locally per CTA (no prep kernel, no flags).
    extern __shared__ char sb[];
    float* sZ  = (float*)(sb + S_Z2);     // stride 129
    float* sA  = (float*)(sb + S_AVEC);
    float* sS  = (float*)(sb + S_SS);
    float* sSp = (float*)(sb + S_SP);
    float* cs  = (float*)(sb + S_CTRL + 16);
    const int tid = threadIdx.x;
    const int tile = blockIdx.x;
    const int b = blockIdx.y;
    const int r = tid >> 1;
    const int half = tid & 1;
    const int cb = half * 64;

    // local a/c
    {
        float* red = sSp;                      // scratch (re-used later)
        float* sq  = (float*)(sb + S_SP + 1024);
        int tt = tid & 127, p = tid >> 7;
        int c0 = p * 64;
        float acc = 0.f;
        for (int c = 0; c < 64; c++)
            acc = fmaf(embed[c0 + c], Wq[(c0 + c) * 128 + tt], acc);
        red[p * 128 + tt] = acc;
        __syncthreads();
        if (tid < 128) sq[tid] = bq[tid] + red[tid] + red[128 + tid];
        __syncthreads();
        {
            int h = tid >> 7;
            float a = 0.f;
            for (int d = 0; d < 64; d++)
                a = fmaf(Wk[tt * 128 + h * 64 + d], sq[h * 64 + d], a);
            sA[h * 128 + tt] = a;
        }
        if (tid < 2) {
            float cc = 0.f;
            for (int d = 0; d < 64; d++) cc = fmaf(bk[tid * 64 + d], sq[tid * 64 + d], cc);
            cs[tid] = cc;
        }
        __syncthreads();
    }

    float ur[64];
    {
        const float4* up = (const float4*)(u + ((size_t)b * SEQN + (size_t)tile * 128 + r) * 64);
        #pragma unroll
        for (int i = 0; i < 16; i++) {
            float4 v = up[i];
            ur[4 * i] = v.x; ur[4 * i + 1] = v.y; ur[4 * i + 2] = v.z; ur[4 * i + 3] = v.w;
        }
    }
    float zr[64];
    #pragma unroll 2
    for (int c = 0; c < 64; c++) {
        float acc = b1[cb + c];
        #pragma unroll 8
        for (int k = 0; k < 64; k++) acc = fmaf(ur[k], W1[k * 128 + cb + c], acc);
        zr[c] = gelu_f(acc);
    }
    for (int c = 0; c < 64; c++) sZ[r * 129 + cb + c] = zr[c];
    __syncthreads();
    #pragma unroll 2
    for (int c = 0; c < 64; c++) {
        float acc = b2[cb + c];
        #pragma unroll 8
        for (int k = 0; k < 128; k++) acc = fmaf(sZ[r * 129 + k], W2[k * 128 + cb + c], acc);
        zr[c] = gelu_f(acc);
    }
    __syncthreads();
    {
        float sp0 = 0.f, sp1 = 0.f;
        for (int c = 0; c < 64; c++) {
            float z = zr[c];
            sZ[r * 129 + cb + c] = z;
            sp0 = fmaf(sA[cb + c], z, sp0);
            sp1 = fmaf(sA[128 + cb + c], z, sp1);
        }
        sSp[r * 4 + half * 2 + 0] = sp0;
        sSp[r * 4 + half * 2 + 1] = sp1;
    }
    __syncthreads();
    {
        int r2 = tid >> 1, h = tid & 1;
        sS[r2 * 2 + h] = cs[h] + sSp[r2 * 4 + h] + sSp[r2 * 4 + 2 + h];
    }
    __syncthreads();
    {
        int h = tid >> 7, col = tid & 127;
        float m = 0.f;
        #pragma unroll 4
        for (int rr = 0; rr < 128; rr++) m = fmaf(sS[rr * 2 + h], sZ[rr * 129 + col], m);
        g_mp[((size_t)(tile * BATCH + b)) * 256 + tid] = m;
        if (tid < 2) {
            float S = 0.f;
            #pragma unroll 4
            for (int rr = 0; rr < 128; rr++) S += sS[rr * 2 + tid];
            g_Sp[(tile * BATCH + b) * 2 + tid] = S;
        }
    }
#endif
}

// ---------------- finish: MLP-optimized reduce + V-proj + O-proj ----------------
// 256 threads/block. Each output of the two GEMVs is split across 2 threads
// (half the 128-d dot each) so per-thread load chains are 64 fully-unrolled
// independent loads instead of 128 at unroll 4.
__global__ void __launch_bounds__(256, 1)
finish_kernel(const float* __restrict__ Wv, const float* __restrict__ bv,
              const float* __restrict__ Wo, const float* __restrict__ bo,
              float* __restrict__ out) {
    __shared__ float sm[256];
    __shared__ float red[256];
    __shared__ float sSs[2];
    __shared__ float sop[128];
    int b = blockIdx.x;
    int t = threadIdx.x;       // 0..255
    if (b == 0 && t == 0) g_ready = 0;   // re-arm bootstrap for the next call

    // phase A: reduce partials; col = t (0..255), 32 independent loads
    {
        float m = 0.f;
        #pragma unroll
        for (int tile = 0; tile < TILES; tile++)
            m += g_mp[((size_t)(tile * BATCH + b)) * 256 + t];
        sm[t] = m;
        if (t < 2) {
            float S = 0.f;
            #pragma unroll
            for (int tile = 0; tile < TILES; tile++) S += g_Sp[(tile * BATCH + b) * 2 + t];
            sSs[t] = S;
        }
    }
    __syncthreads();

    const int o = t & 127;     // output index
    const int dh = t >> 7;     // d-half: 0 or 1
    const int d0 = dh * 64;

    // phase B: V-proj halves: red[t] = sum_{d in half} sm[h_o*128+d] * Wv[d*128+o]
    {
        const int h = o >> 6;
        const float* smh = sm + h * 128 + d0;
        const float* wv = Wv + (size_t)d0 * 128 + o;
        float acc = 0.f;
        #pragma unroll
        for (int d = 0; d < 64; d++) acc = fmaf(smh[d], wv[(size_t)d * 128], acc);
        red[t] = acc;
    }
    __syncthreads();
    if (t < 128) {
        int h = t >> 6;
        sop[t] = (red[t] + red[128 + t] + sSs[h] * bv[t]) * (1.0f / (float)SEQN);
    }
    __syncthreads();

    // phase C: O-proj halves: red[t] = sum_{j in half} sop[j] * Wo[j*128+o]
    {
        const float* sj = sop + d0;
        const float* wo = Wo + (size_t)d0 * 128 + o;
        float acc = 0.f;
        #pragma unroll
        for (int j = 0; j < 64; j++) acc = fmaf(sj[j], wo[(size_t)j * 128], acc);
        red[t] = acc;
    }
    __syncthreads();
    if (t < 128) {
        out[b * 128 + t] = bo[t] + red[t] + red[128 + t];
    }
}

// ---------------- launch ----------------
extern "C" void kernel_launch(void* const* d_in, const int* in_sizes, int n_in,
                              void* d_out, int out_size) {
    const float* u     = (const float*)d_in[0];
    // d_in[1] = x, unused by the reference output
    const float* W1    = (const float*)d_in[2];
    const float* b1    = (const float*)d_in[3];
    const float* W2    = (const float*)d_in[4];
    const float* b2    = (const float*)d_in[5];
    const float* embed = (const float*)d_in[6];
    const float* Wq    = (const float*)d_in[7];
    const float* bq    = (const float*)d_in[8];
    const float* Wk    = (const float*)d_in[9];
    const float* bk    = (const float*)d_in[10];
    const float* Wv    = (const float*)d_in[11];
    const float* bv    = (const float*)d_in[12];
    const float* Wo    = (const float*)d_in[13];
    const float* bo    = (const float*)d_in[14];
    float* out = (float*)d_out;

    cudaFuncSetAttribute(main_kernel, cudaFuncAttributeMaxDynamicSharedMemorySize, S_TOTAL);

    main_kernel<<<dim3(TILES, BATCH), 256, S_TOTAL>>>(u, W1, b1, W2, b2,
                                                      embed, Wq, bq, Wk, bk);
    finish_kernel<<<BATCH, 256>>>(Wv, bv, Wo, bo, out);
}

// round 16
// speedup vs baseline: 1.4243x; 1.4243x over previous
#include <cuda_runtime.h>
#include <cuda_bf16.h>
#include <cstdint>
#include <cstddef>

// Problem constants: B=32, N=4096, D_U=64, D=128, H=2, DH=64
#define BATCH 32
#define SEQN 4096
#define TILES 32
#define NWORK (TILES * BATCH)

typedef unsigned long long ULL;

// ---- arch-feature gate: tcgen05 only exists on 'a'/'f' suffixed targets ----
#if defined(__CUDA_ARCH__) && (__CUDA_ARCH__ >= 1000) && \
    (defined(__CUDA_ARCH_FEAT_SM103_ALL) || defined(__CUDA_ARCH_FEAT_SM100_ALL) || \
     defined(__CUDA_ARCH_SPECIFIC__) || defined(__CUDA_ARCH_FAMILY_SPECIFIC__))
#define TC_OK 1
#else
#define TC_OK 0
#endif

// ---------------- TMEM column layout: 512 cols ----------------
#define T_A2HI 0
#define T_A2LO 64
#define T_D1   128
#define T_D2   256
#define TMEM_COLS 512

// ---------------- SMEM layout (bytes), R6-style: 1 CTA/SM ----------------
#define S_A1HI 0          /* 16 KB, dead after GEMM1 */
#define S_A1LO 16384      /* 16 KB */
#define S_B1HI 32768      /* 16 KB, dead after GEMM1 */
#define S_B1LO 49152      /* 16 KB */
#define S_Z2   0          /* fp32 z2, 128 x stride129 = 66048 B (overlays A1/B1) */
#define S_B2HI 66560      /* 32 KB, separate region -> conversion overlaps GEMM1 */
#define S_B2LO 99328      /* 32 KB */
#define S_AVEC 132096     /* a_h vectors: 2 x 128 fp32 */
#define S_SS   133120     /* scores 128 x 2 fp32 */
#define S_SP   134144     /* score partials (2048 B); also boot a/c scratch */
#define S_CTRL 136192     /* tmem ptr @0, mbar @8, c[2] @16 */
#define S_B1B  136256     /* b1 128 fp32 */
#define S_B2B  136768     /* b2 128 fp32 */
#define S_TOTAL 137280

// idesc: F32 accum, BF16 a/b, N=128, M=128, cta_group::1
#define IDESC ((1u<<4)|(1u<<7)|(1u<<10)|(16u<<17)|(8u<<24))

// ---------------- global scratch (no allocations allowed) ----------------
__device__ float g_a[2 * 128];
__device__ float g_c[2];
__device__ float g_mp[NWORK * 256];
__device__ float g_Sp[NWORK * 2];
__device__ int g_ready;     // a/c-published flag; reset by finish_kernel

// ---------------- common helpers ----------------
__device__ __forceinline__ float gelu_f(float x) {
    float x2 = x * x;
    float inner = fmaf(0.044715f * x2, x, x);
    float arg = 0.7978845608028654f * inner;
    float t;
    asm("tanh.approx.f32 %0, %1;" : "=f"(t) : "f"(arg));
    return 0.5f * x * (1.0f + t);
}
__device__ __forceinline__ uint32_t swz(uint32_t byte_off) {
    return byte_off ^ ((byte_off >> 3) & 0x70);
}
__device__ __forceinline__ uint32_t pk_bf(float a, float b) {
    return (uint32_t)__bfloat16_as_ushort(__float2bfloat16_rn(a)) |
           ((uint32_t)__bfloat16_as_ushort(__float2bfloat16_rn(b)) << 16);
}

#if TC_OK
// ---------------- tcgen05 PTX helpers (only compiled on 'a'/'f' targets) ----
__device__ __forceinline__ uint32_t elect_one_pred() {
    uint32_t pred;
    asm volatile(
        "{\n\t.reg .pred p;\n\telect.sync _|p, 0xFFFFFFFF;\n\t"
        "selp.b32 %0, 1, 0, p;\n\t}" : "=r"(pred));
    return pred;
}
__device__ __forceinline__ uint32_t smem_to_u32(const void* p) {
    uint32_t a;
    asm("{ .reg .u64 t; cvta.to.shared.u64 t, %1; cvt.u32.u64 %0, t; }" : "=r"(a) : "l"(p));
    return a;
}
static constexpr uint64_t SMEM_DESC_BASE_SW128 =
    (uint64_t(2) << 61) | (uint64_t(1) << 46) | (uint64_t(64) << 32) | (uint64_t(1) << 16);
#define MAKE_SMEM_DESC(base_addr) \
    (SMEM_DESC_BASE_SW128 | ((uint64_t)((base_addr) >> 4) & 0x3FFF))

#define TCGEN05_ALLOC(smem_addr, nCols) \
    asm volatile("tcgen05.alloc.cta_group::1.sync.aligned.shared::cta.b32 [%0], %1;" \
        :: "r"((uint32_t)(smem_addr)), "r"((uint32_t)(nCols)) : "memory")
#define TCGEN05_DEALLOC(tmem_addr, nCols) \
    asm volatile("tcgen05.dealloc.cta_group::1.sync.aligned.b32 %0, %1;" \
        :: "r"(tmem_addr), "r"((uint32_t)(nCols)))
#define TCGEN05_COMMIT(mbar) \
    asm volatile("tcgen05.commit.cta_group::1.mbarrier::arrive::one.shared::cluster.b64 [%0];" \
        :: "r"((uint32_t)(mbar)) : "memory")
#define TCGEN05_WAIT_LD()  asm volatile("tcgen05.wait::ld.sync.aligned;" ::: "memory")
#define TCGEN05_WAIT_ST()  asm volatile("tcgen05.wait::st.sync.aligned;" ::: "memory")
#define TCGEN05_FENCE_BEFORE() asm volatile("tcgen05.fence::before_thread_sync;" ::: "memory")
#define TCGEN05_FENCE_AFTER()  asm volatile("tcgen05.fence::after_thread_sync;" ::: "memory")
#define MBARRIER_INIT(mbar, count) \
    asm volatile("mbarrier.init.shared.b64 [%0], %1;" \
        :: "r"((uint32_t)(mbar)), "r"((uint32_t)(count)) : "memory")
#define MBARRIER_INVAL(mbar) \
    asm volatile("mbarrier.inval.shared.b64 [%0];" :: "r"((uint32_t)(mbar)) : "memory")

#define MBARRIER_WAIT_PARITY(mbar_smem_addr, phase_parity) do { \
    uint32_t _mbar = (uint32_t)(mbar_smem_addr); \
    uint32_t _parity = (uint32_t)(phase_parity); \
    uint32_t _done; \
    asm volatile( \
        "{\n\t.reg .pred p;\n\t" \
        "mbarrier.try_wait.parity.acquire.cta.shared::cta.b64 p, [%1], %2;\n\t" \
        "selp.b32 %0, 1, 0, p;\n\t}" \
        : "=r"(_done) : "r"(_mbar), "r"(_parity) : "memory"); \
    if (!_done) { \
        asm volatile( \
            "{\n\t.reg .pred P1;\n\t" \
            "WAIT_LOOP_%=:\n\t" \
            "mbarrier.try_wait.parity.acquire.cta.shared::cta.b64 P1, [%0], %1, 0x989680;\n\t" \
            "@P1 bra.uni WAIT_DONE_%=;\n\t" \
            "bra.uni WAIT_LOOP_%=;\n\t" \
            "WAIT_DONE_%=:\n\t}" \
            :: "r"(_mbar), "r"(_parity) : "memory"); \
    } \
} while (0)

#define TCGEN05_LD_32X32B_X32(r, tmem_addr) \
    asm volatile( \
        "tcgen05.ld.sync.aligned.32x32b.x32.b32 " \
        "{%0, %1, %2, %3, %4, %5, %6, %7, " \
        " %8, %9, %10, %11, %12, %13, %14, %15, " \
        " %16, %17, %18, %19, %20, %21, %22, %23, " \
        " %24, %25, %26, %27, %28, %29, %30, %31}, [%32];" \
        : "=r"((r)[0]),  "=r"((r)[1]),  "=r"((r)[2]),  "=r"((r)[3]), \
          "=r"((r)[4]),  "=r"((r)[5]),  "=r"((r)[6]),  "=r"((r)[7]), \
          "=r"((r)[8]),  "=r"((r)[9]),  "=r"((r)[10]), "=r"((r)[11]), \
          "=r"((r)[12]), "=r"((r)[13]), "=r"((r)[14]), "=r"((r)[15]), \
          "=r"((r)[16]), "=r"((r)[17]), "=r"((r)[18]), "=r"((r)[19]), \
          "=r"((r)[20]), "=r"((r)[21]), "=r"((r)[22]), "=r"((r)[23]), \
          "=r"((r)[24]), "=r"((r)[25]), "=r"((r)[26]), "=r"((r)[27]), \
          "=r"((r)[28]), "=r"((r)[29]), "=r"((r)[30]), "=r"((r)[31]) \
        : "r"(tmem_addr))

#define TCGEN05_ST_32X32B_X16(tmem_addr, r) \
    asm volatile( \
        "tcgen05.st.sync.aligned.32x32b.x16.b32 [%0], " \
        "{%1, %2, %3, %4, %5, %6, %7, %8, " \
        " %9, %10, %11, %12, %13, %14, %15, %16};" \
        :: "r"(tmem_addr), \
           "r"((r)[0]),  "r"((r)[1]),  "r"((r)[2]),  "r"((r)[3]), \
           "r"((r)[4]),  "r"((r)[5]),  "r"((r)[6]),  "r"((r)[7]), \
           "r"((r)[8]),  "r"((r)[9]),  "r"((r)[10]), "r"((r)[11]), \
           "r"((r)[12]), "r"((r)[13]), "r"((r)[14]), "r"((r)[15]) \
        : "memory")

__device__ __forceinline__ void mma_f16_ss(uint32_t d, uint64_t ad, uint64_t bd,
                                           uint32_t idesc, uint32_t en) {
    asm volatile(
        "{\n\t.reg .pred p;\n\tsetp.ne.u32 p, %4, 0;\n\t"
        "tcgen05.mma.cta_group::1.kind::f16 [%0], %1, %2, %3, {%5, %5, %5, %5}, p;\n\t}"
        :: "r"(d), "l"(ad), "l"(bd), "r"(idesc), "r"(en), "r"(0u) : "memory");
}
__device__ __forceinline__ void mma_f16_ts(uint32_t d, uint32_t at, uint64_t bd,
                                           uint32_t idesc, uint32_t en) {
    asm volatile(
        "{\n\t.reg .pred p;\n\tsetp.ne.u32 p, %4, 0;\n\t"
        "tcgen05.mma.cta_group::1.kind::f16 [%0], [%1], %2, %3, {%5, %5, %5, %5}, p;\n\t}"
        :: "r"(d), "r"(at), "l"(bd), "r"(idesc), "r"(en), "r"(0u) : "memory");
}
#endif  // TC_OK

// ---------------- main kernel: no prep launch, no front spin ----------------
// Every CTA converts W1/W2 fp32 -> split-bf16 swizzled smem images locally
// (same L2 bytes as copying prebuilt images; W2 conversion overlaps GEMM1).
// CTA(0,0) additionally computes the a/c fold vectors FIRST and publishes;
// consumers check the flag only at epilogue-2 (first use), ~10us later.
__global__ void __launch_bounds__(256, 1)
main_kernel(const float* __restrict__ u,
            const float* __restrict__ W1, const float* __restrict__ b1,
            const float* __restrict__ W2, const float* __restrict__ b2,
            const float* __restrict__ embed,
            const float* __restrict__ Wq, const float* __restrict__ bq,
            const float* __restrict__ Wk, const float* __restrict__ bk) {
#if TC_OK
    extern __shared__ char sb[];
    const int tid = threadIdx.x;
    const int w = tid >> 5;
    const int lane = tid & 31;
    const int tile = blockIdx.x;
    const int b = blockIdx.y;
    const bool boot = (tile == 0) && (b == 0);
    uint32_t sb32 = smem_to_u32(sb);

    if (w == 0) TCGEN05_ALLOC(sb32 + S_CTRL, TMEM_COLS);
    if (tid == 0) MBARRIER_INIT(sb32 + S_CTRL + 8, 1);

    // ---- boot CTA: a/c fold vectors first, publish ASAP ----
    if (boot) {
        float* red = (float*)(sb + S_SP);
        float* sq  = (float*)(sb + S_SP + 1024);
        {
            int tt = tid & 127, p = tid >> 7;
            int c0 = p * 64;
            float acc = 0.f;
            #pragma unroll
            for (int c = 0; c < 64; c++)
                acc = fmaf(embed[c0 + c], Wq[(c0 + c) * 128 + tt], acc);
            red[p * 128 + tt] = acc;
        }
        __syncthreads();
        if (tid < 128) sq[tid] = bq[tid] + red[tid] + red[128 + tid];
        __syncthreads();
        {
            int tt = tid & 127, h = tid >> 7;
            float a = 0.f;
            #pragma unroll
            for (int d = 0; d < 64; d++)
                a = fmaf(Wk[tt * 128 + h * 64 + d], sq[h * 64 + d], a);
            g_a[h * 128 + tt] = a;
        }
        if (tid < 2) {
            float c0 = 0.f;
            #pragma unroll
            for (int d = 0; d < 64; d++) c0 = fmaf(bk[tid * 64 + d], sq[tid * 64 + d], c0);
            g_c[tid] = c0;
        }
        __threadfence();
        __syncthreads();
        if (tid == 0)
            asm volatile("st.release.gpu.global.b32 [%0], %1;" :: "l"(&g_ready), "r"(1) : "memory");
    }

    // ---- phase 0a: u tile -> split-bf16 A1 (SW128 K-major) ----
    {
        int row = tid >> 1, kh = (tid & 1) << 5;
        const float4* up = (const float4*)(u + ((size_t)b * SEQN + (size_t)tile * 128 + row) * 64 + kh);
        #pragma unroll
        for (int i = 0; i < 8; i++) {
            float4 v = up[i];
            __nv_bfloat16 h0 = __float2bfloat16_rn(v.x), h1 = __float2bfloat16_rn(v.y);
            __nv_bfloat16 h2 = __float2bfloat16_rn(v.z), h3 = __float2bfloat16_rn(v.w);
            uint32_t hiA = (uint32_t)__bfloat16_as_ushort(h0) | ((uint32_t)__bfloat16_as_ushort(h1) << 16);
            uint32_t hiB = (uint32_t)__bfloat16_as_ushort(h2) | ((uint32_t)__bfloat16_as_ushort(h3) << 16);
            uint32_t loA = pk_bf(v.x - __bfloat162float(h0), v.y - __bfloat162float(h1));
            uint32_t loB = pk_bf(v.z - __bfloat162float(h2), v.w - __bfloat162float(h3));
            uint32_t sw = swz((uint32_t)(row * 128 + (kh + 4 * i) * 2));
            *(ULL*)(sb + S_A1HI + sw) = (ULL)hiA | ((ULL)hiB << 32);
            *(ULL*)(sb + S_A1LO + sw) = (ULL)loA | ((ULL)loB << 32);
        }
    }
    // ---- phase 0b: W1 fp32 -> B1 split-bf16 image (local, coalesced reads) ----
    // B1[n][k] = W1[k][n], K-major bf16 rows of 128B, SW128 swizzled.
    {
        #pragma unroll 8
        for (int i = 0; i < 32; i++) {
            int idx = tid + 256 * i;            // k = idx>>7, n = idx&127
            int k = idx >> 7, n = idx & 127;
            float wv = W1[idx];
            __nv_bfloat16 h = __float2bfloat16_rn(wv);
            __nv_bfloat16 l = __float2bfloat16_rn(wv - __bfloat162float(h));
            uint32_t loc = swz((uint32_t)(n * 128 + k * 2));
            *(__nv_bfloat16*)(sb + S_B1HI + loc) = h;
            *(__nv_bfloat16*)(sb + S_B1LO + loc) = l;
        }
    }
    if (tid < 128) {
        ((float*)(sb + S_B1B))[tid] = b1[tid];
        ((float*)(sb + S_B2B))[tid] = b2[tid];
    }
    asm volatile("fence.proxy.async.shared::cta;" ::: "memory");
    __syncthreads();

    uint32_t tbase;
    asm volatile("ld.shared.b32 %0, [%1];" : "=r"(tbase) : "r"(sb32 + S_CTRL));

    // ---- GEMM1: D1 = A1 @ B1^T  (3 split terms x 4 K-chunks, SS mode) ----
    if (w == 0) {
        uint64_t aH = MAKE_SMEM_DESC(sb32 + S_A1HI), aL = MAKE_SMEM_DESC(sb32 + S_A1LO);
        uint64_t bH = MAKE_SMEM_DESC(sb32 + S_B1HI), bL = MAKE_SMEM_DESC(sb32 + S_B1LO);
        if (elect_one_pred()) {
            #pragma unroll
            for (int k = 0; k < 4; k++) mma_f16_ss(tbase + T_D1, aH + 2 * k, bH + 2 * k, IDESC, k > 0);
            #pragma unroll
            for (int k = 0; k < 4; k++) mma_f16_ss(tbase + T_D1, aH + 2 * k, bL + 2 * k, IDESC, 1);
            #pragma unroll
            for (int k = 0; k < 4; k++) mma_f16_ss(tbase + T_D1, aL + 2 * k, bH + 2 * k, IDESC, 1);
            TCGEN05_COMMIT(sb32 + S_CTRL + 8);
        }
    }
    // ---- W2 fp32 -> B2 split-bf16 image while GEMM1 runs (separate region) ----
    // Blocked SW128 atoms: atom_col = k>>6 at +16KB.
    {
        #pragma unroll 8
        for (int i = 0; i < 64; i++) {
            int idx = tid + 256 * i;            // k = idx>>7, n = idx&127
            int k = idx >> 7, n = idx & 127;
            float wv = W2[idx];
            __nv_bfloat16 h = __float2bfloat16_rn(wv);
            __nv_bfloat16 l = __float2bfloat16_rn(wv - __bfloat162float(h));
            uint32_t byte = ((uint32_t)(k >> 6) << 14) + ((uint32_t)(n >> 3) << 10)
                          + ((uint32_t)(n & 7) << 7) + ((uint32_t)(k & 63) << 1);
            uint32_t loc = swz(byte);
            *(__nv_bfloat16*)(sb + S_B2HI + loc) = h;
            *(__nv_bfloat16*)(sb + S_B2LO + loc) = l;
        }
    }
    asm volatile("fence.proxy.async.shared::cta;" ::: "memory");

    MBARRIER_WAIT_PARITY(sb32 + S_CTRL + 8, 0);
    TCGEN05_FENCE_AFTER();

    // ---- epilogue 1: z1 = gelu(D1+b1) -> split bf16 -> TMEM A2 (TS operand) ----
    const int part = w & 3;
    const int cbase = (w >> 2) * 64;
    const int r = part * 32 + lane;
    const uint32_t sttm = ((uint32_t)part) << 21;
    {
        const float* b1s = (const float*)(sb + S_B1B);
        #pragma unroll
        for (int ch = 0; ch < 2; ch++) {
            int c0 = cbase + 32 * ch;
            uint32_t d[32];
            TCGEN05_LD_32X32B_X32(d, tbase + T_D1 + c0);
            TCGEN05_WAIT_LD();
            uint32_t hi[16], lo[16];
            #pragma unroll
            for (int j = 0; j < 16; j++) {
                float z0 = gelu_f(__uint_as_float(d[2 * j]) + b1s[c0 + 2 * j]);
                float z1 = gelu_f(__uint_as_float(d[2 * j + 1]) + b1s[c0 + 2 * j + 1]);
                __nv_bfloat16 h0 = __float2bfloat16_rn(z0), h1 = __float2bfloat16_rn(z1);
                hi[j] = (uint32_t)__bfloat16_as_ushort(h0) | ((uint32_t)__bfloat16_as_ushort(h1) << 16);
                lo[j] = pk_bf(z0 - __bfloat162float(h0), z1 - __bfloat162float(h1));
            }
            TCGEN05_ST_32X32B_X16(tbase + T_A2HI + (c0 >> 1) + sttm, hi);
            TCGEN05_ST_32X32B_X16(tbase + T_A2LO + (c0 >> 1) + sttm, lo);
        }
        TCGEN05_WAIT_ST();
    }
    TCGEN05_FENCE_BEFORE();
    __syncthreads();   // all LDTM of D1 done; A2 + B2 ready

    // ---- GEMM2: D2 = A2 @ B2^T  (3 split terms x 8 K-chunks, TS mode) ----
    if (w == 0) {
        TCGEN05_FENCE_AFTER();
        uint64_t bH = MAKE_SMEM_DESC(sb32 + S_B2HI), bL = MAKE_SMEM_DESC(sb32 + S_B2LO);
        if (elect_one_pred()) {
            #pragma unroll
            for (int k = 0; k < 8; k++) {
                uint64_t o = (k < 4) ? (uint64_t)(2 * k) : (uint64_t)(1024 + 2 * (k - 4));
                mma_f16_ts(tbase + T_D2, tbase + T_A2HI + 8 * k, bH + o, IDESC, k > 0);
            }
            #pragma unroll
            for (int k = 0; k < 8; k++) {
                uint64_t o = (k < 4) ? (uint64_t)(2 * k) : (uint64_t)(1024 + 2 * (k - 4));
                mma_f16_ts(tbase + T_D2, tbase + T_A2HI + 8 * k, bL + o, IDESC, 1);
            }
            #pragma unroll
            for (int k = 0; k < 8; k++) {
                uint64_t o = (k < 4) ? (uint64_t)(2 * k) : (uint64_t)(1024 + 2 * (k - 4));
                mma_f16_ts(tbase + T_D2, tbase + T_A2LO + 8 * k, bH + o, IDESC, 1);
            }
            TCGEN05_COMMIT(sb32 + S_CTRL + 8);
        }
    }
    MBARRIER_WAIT_PARITY(sb32 + S_CTRL + 8, 1);
    TCGEN05_FENCE_AFTER();

    // ---- acquire a/c (flag is ~10us old by now; spin is fast-path) ----
    if (tid == 0) {
        int v;
        do {
            asm volatile("ld.acquire.gpu.global.b32 %0, [%1];" : "=r"(v) : "l"(&g_ready) : "memory");
            if (!v) __nanosleep(32);
        } while (!v);
    }
    __syncthreads();
    ((float*)(sb + S_AVEC))[tid] = g_a[tid];
    if (tid < 2) ((float*)(sb + S_CTRL + 16))[tid] = g_c[tid];
    __syncthreads();

    // ---- epilogue 2: z2 = gelu(D2+b2); score partials; z2 -> smem (stride 129) ----
    {
        float* z2s = (float*)(sb + S_Z2);
        const float* av = (const float*)(sb + S_AVEC);
        const float* b2s = (const float*)(sb + S_B2B);
        float sp0 = 0.f, sp1 = 0.f;
        #pragma unroll
        for (int ch = 0; ch < 2; ch++) {
            int c0 = cbase + 32 * ch;
            uint32_t d[32];
            TCGEN05_LD_32X32B_X32(d, tbase + T_D2 + c0);
            TCGEN05_WAIT_LD();
            #pragma unroll
            for (int j = 0; j < 32; j++) {
                float z = gelu_f(__uint_as_float(d[j]) + b2s[c0 + j]);
                z2s[r * 129 + c0 + j] = z;
                sp0 = fmaf(av[c0 + j], z, sp0);
                sp1 = fmaf(av[128 + c0 + j], z, sp1);
            }
        }
        float* sSp = (float*)(sb + S_SP);
        sSp[r * 4 + (w >> 2) * 2 + 0] = sp0;
        sSp[r * 4 + (w >> 2) * 2 + 1] = sp1;
    }
    __syncthreads();

    // combine score halves: s[r][h] = c_h + sp[r][0][h] + sp[r][1][h]
    {
        float* sS = (float*)(sb + S_SS);
        const float* sSp = (const float*)(sb + S_SP);
        const float* cs = (const float*)(sb + S_CTRL + 16);
        int r2 = tid >> 1, h = tid & 1;
        sS[r2 * 2 + h] = cs[h] + sSp[r2 * 4 + h] + sSp[r2 * 4 + 2 + h];
    }
    __syncthreads();

    // phase 4: m_h[col] = sum_r s[r][h] * z2[r][col]
    {
        const float* sS = (const float*)(sb + S_SS);
        const float* z2s = (const float*)(sb + S_Z2);
        int h = tid >> 7, col = tid & 127;
        float m = 0.f;
        #pragma unroll 4
        for (int rr = 0; rr < 128; rr++) m = fmaf(sS[rr * 2 + h], z2s[rr * 129 + col], m);
        g_mp[((size_t)(tile * BATCH + b)) * 256 + tid] = m;
        if (tid < 2) {
            float S = 0.f;
            #pragma unroll 4
            for (int rr = 0; rr < 128; rr++) S += sS[rr * 2 + tid];
            g_Sp[(tile * BATCH + b) * 2 + tid] = S;
        }
    }

    __syncthreads();
    if (tid == 0) MBARRIER_INVAL(sb32 + S_CTRL + 8);
    __syncthreads();
    if (w == 0) TCGEN05_DEALLOC(tbase, TMEM_COLS);

#else
    // ================= compact fallback (never runs on sm_103a) =================
    // Computes a/c locally per CTA (no flags).
    extern __shared__ char sb[];
    float* sZ  = (float*)(sb + S_Z2);     // stride 129
    float* sA  = (float*)(sb + S_AVEC);
    float* sS  = (float*)(sb + S_SS);
    float* sSp = (float*)(sb + S_SP);
    float* cs  = (float*)(sb + S_CTRL + 16);
    const int tid = threadIdx.x;
    const int tile = blockIdx.x;
    const int b = blockIdx.y;
    const int r = tid >> 1;
    const int half = tid & 1;
    const int cb = half * 64;

    // local a/c
    {
        float* red = sSp;                      // scratch (re-used later)
        float* sq  = (float*)(sb + S_SP + 1024);
        int tt = tid & 127, p = tid >> 7;
        int c0 = p * 64;
        float acc = 0.f;
        for (int c = 0; c < 64; c++)
            acc = fmaf(embed[c0 + c], Wq[(c0 + c) * 128 + tt], acc);
        red[p * 128 + tt] = acc;
        __syncthreads();
        if (tid < 128) sq[tid] = bq[tid] + red[tid] + red[128 + tid];
        __syncthreads();
        {
            int h = tid >> 7;
            float a = 0.f;
            for (int d = 0; d < 64; d++)
                a = fmaf(Wk[tt * 128 + h * 64 + d], sq[h * 64 + d], a);
            sA[h * 128 + tt] = a;
        }
        if (tid < 2) {
            float cc = 0.f;
            for (int d = 0; d < 64; d++) cc = fmaf(bk[tid * 64 + d], sq[tid * 64 + d], cc);
            cs[tid] = cc;
        }
        __syncthreads();
    }

    float ur[64];
    {
        const float4* up = (const float4*)(u + ((size_t)b * SEQN + (size_t)tile * 128 + r) * 64);
        #pragma unroll
        for (int i = 0; i < 16; i++) {
            float4 v = up[i];
            ur[4 * i] = v.x; ur[4 * i + 1] = v.y; ur[4 * i + 2] = v.z; ur[4 * i + 3] = v.w;
        }
    }
    float zr[64];
    #pragma unroll 2
    for (int c = 0; c < 64; c++) {
        float acc = b1[cb + c];
        #pragma unroll 8
        for (int k = 0; k < 64; k++) acc = fmaf(ur[k], W1[k * 128 + cb + c], acc);
        zr[c] = gelu_f(acc);
    }
    for (int c = 0; c < 64; c++) sZ[r * 129 + cb + c] = zr[c];
    __syncthreads();
    #pragma unroll 2
    for (int c = 0; c < 64; c++) {
        float acc = b2[cb + c];
        #pragma unroll 8
        for (int k = 0; k < 128; k++) acc = fmaf(sZ[r * 129 + k], W2[k * 128 + cb + c], acc);
        zr[c] = gelu_f(acc);
    }
    __syncthreads();
    {
        float sp0 = 0.f, sp1 = 0.f;
        for (int c = 0; c < 64; c++) {
            float z = zr[c];
            sZ[r * 129 + cb + c] = z;
            sp0 = fmaf(sA[cb + c], z, sp0);
            sp1 = fmaf(sA[128 + cb + c], z, sp1);
        }
        sSp[r * 4 + half * 2 + 0] = sp0;
        sSp[r * 4 + half * 2 + 1] = sp1;
    }
    __syncthreads();
    {
        int r2 = tid >> 1, h = tid & 1;
        sS[r2 * 2 + h] = cs[h] + sSp[r2 * 4 + h] + sSp[r2 * 4 + 2 + h];
    }
    __syncthreads();
    {
        int h = tid >> 7, col = tid & 127;
        float m = 0.f;
        #pragma unroll 4
        for (int rr = 0; rr < 128; rr++) m = fmaf(sS[rr * 2 + h], sZ[rr * 129 + col], m);
        g_mp[((size_t)(tile * BATCH + b)) * 256 + tid] = m;
        if (tid < 2) {
            float S = 0.f;
            #pragma unroll 4
            for (int rr = 0; rr < 128; rr++) S += sS[rr * 2 + tid];
            g_Sp[(tile * BATCH + b) * 2 + tid] = S;
        }
    }
#endif
}

// ---------------- finish: MLP-optimized reduce + V-proj + O-proj ----------------
__global__ void __launch_bounds__(256, 1)
finish_kernel(const float* __restrict__ Wv, const float* __restrict__ bv,
              const float* __restrict__ Wo, const float* __restrict__ bo,
              float* __restrict__ out) {
    __shared__ float sm[256];
    __shared__ float red[256];
    __shared__ float sSs[2];
    __shared__ float sop[128];
    int b = blockIdx.x;
    int t = threadIdx.x;       // 0..255
    if (b == 0 && t == 0) g_ready = 0;   // re-arm a/c flag for the next call

    // phase A: reduce partials; col = t (0..255), 32 independent loads
    {
        float m = 0.f;
        #pragma unroll
        for (int tile = 0; tile < TILES; tile++)
            m += g_mp[((size_t)(tile * BATCH + b)) * 256 + t];
        sm[t] = m;
        if (t < 2) {
            float S = 0.f;
            #pragma unroll
            for (int tile = 0; tile < TILES; tile++) S += g_Sp[(tile * BATCH + b) * 2 + t];
            sSs[t] = S;
        }
    }
    __syncthreads();

    const int o = t & 127;     // output index
    const int dh = t >> 7;     // d-half: 0 or 1
    const int d0 = dh * 64;

    // phase B: V-proj halves
    {
        const int h = o >> 6;
        const float* smh = sm + h * 128 + d0;
        const float* wv = Wv + (size_t)d0 * 128 + o;
        float acc = 0.f;
        #pragma unroll
        for (int d = 0; d < 64; d++) acc = fmaf(smh[d], wv[(size_t)d * 128], acc);
        red[t] = acc;
    }
    __syncthreads();
    if (t < 128) {
        int h = t >> 6;
        sop[t] = (red[t] + red[128 + t] + sSs[h] * bv[t]) * (1.0f / (float)SEQN);
    }
    __syncthreads();

    // phase C: O-proj halves
    {
        const float* sj = sop + d0;
        const float* wo = Wo + (size_t)d0 * 128 + o;
        float acc = 0.f;
        #pragma unroll
        for (int j = 0; j < 64; j++) acc = fmaf(sj[j], wo[(size_t)j * 128], acc);
        red[t] = acc;
    }
    __syncthreads();
    if (t < 128) {
        out[b * 128 + t] = bo[t] + red[t] + red[128 + t];
    }
}

// ---------------- launch ----------------
extern "C" void kernel_launch(void* const* d_in, const int* in_sizes, int n_in,
                              void* d_out, int out_size) {
    const float* u     = (const float*)d_in[0];
    // d_in[1] = x, unused by the reference output
    const float* W1    = (const float*)d_in[2];
    const float* b1    = (const float*)d_in[3];
    const float* W2    = (const float*)d_in[4];
    const float* b2    = (const float*)d_in[5];
    const float* embed = (const float*)d_in[6];
    const float* Wq    = (const float*)d_in[7];
    const float* bq    = (const float*)d_in[8];
    const float* Wk    = (const float*)d_in[9];
    const float* bk    = (const float*)d_in[10];
    const float* Wv    = (const float*)d_in[11];
    const float* bv    = (const float*)d_in[12];
    const float* Wo    = (const float*)d_in[13];
    const float* bo    = (const float*)d_in[14];
    float* out = (float*)d_out;

    cudaFuncSetAttribute(main_kernel, cudaFuncAttributeMaxDynamicSharedMemorySize, S_TOTAL);

    main_kernel<<<dim3(TILES, BATCH), 256, S_TOTAL>>>(u, W1, b1, W2, b2,
                                                      embed, Wq, bq, Wk, bk);
    finish_kernel<<<BATCH, 256>>>(Wv, bv, Wo, bo, out);
}